// round 15
// baseline (speedup 1.0000x reference)
#include <cuda_runtime.h>
#include <cuda_bf16.h>
#include <cstdint>

// Problem dims
#define Bsz   2
#define Ssz   2048
#define Hsz   2048
#define NHEAD 16
#define HDIM  128
#define Mrows (Bsz*Ssz)   // 4096

typedef __nv_bfloat16 bf16;

// ---------------- scratch (static device globals) ----------------
__device__ float g_ao [Mrows*Hsz];          // attention out (fp32)
__device__ bf16 g_qh [Mrows*Hsz], g_ql [Mrows*Hsz];
__device__ bf16 g_kh [Mrows*Hsz], g_kl [Mrows*Hsz];
__device__ bf16 g_vh [Mrows*Hsz], g_vl [Mrows*Hsz];

// ---------------- helpers ----------------
__device__ __forceinline__ uint32_t smem_u32(const void* p) {
    uint32_t a;
    asm("{ .reg .u64 t; cvta.to.shared.u64 t, %1; cvt.u32.u64 %0, t; }" : "=r"(a) : "l"(p));
    return a;
}
#define CP_ASYNC16(sa, ga) \
    asm volatile("cp.async.cg.shared.global [%0], [%1], 16;" :: "r"((uint32_t)(sa)), "l"(ga))
#define CP_COMMIT() asm volatile("cp.async.commit_group;" ::: "memory")
#define CP_WAIT(n)  asm volatile("cp.async.wait_group %0;" :: "n"(n) : "memory")

__device__ __forceinline__ void ldsm4(uint32_t* r, uint32_t addr) {
    asm volatile("ldmatrix.sync.aligned.m8n8.x4.shared.b16 {%0,%1,%2,%3}, [%4];"
                 : "=r"(r[0]), "=r"(r[1]), "=r"(r[2]), "=r"(r[3]) : "r"(addr));
}
__device__ __forceinline__ void ldsm4t(uint32_t* r, uint32_t addr) {
    asm volatile("ldmatrix.sync.aligned.m8n8.x4.trans.shared.b16 {%0,%1,%2,%3}, [%4];"
                 : "=r"(r[0]), "=r"(r[1]), "=r"(r[2]), "=r"(r[3]) : "r"(addr));
}
// bf16 mma (flash)
__device__ __forceinline__ void mma16816(float* c, const uint32_t* a,
                                         uint32_t b0, uint32_t b1) {
    asm volatile(
        "mma.sync.aligned.m16n8k16.row.col.f32.bf16.bf16.f32 "
        "{%0,%1,%2,%3}, {%4,%5,%6,%7}, {%8,%9}, {%0,%1,%2,%3};"
        : "+f"(c[0]), "+f"(c[1]), "+f"(c[2]), "+f"(c[3])
        : "r"(a[0]), "r"(a[1]), "r"(a[2]), "r"(a[3]), "r"(b0), "r"(b1));
}
// tf32 mma (projections)
__device__ __forceinline__ void mma1688t(float* c, const uint32_t* a,
                                         uint32_t b0, uint32_t b1) {
    asm volatile(
        "mma.sync.aligned.m16n8k8.row.col.f32.tf32.tf32.f32 "
        "{%0,%1,%2,%3}, {%4,%5,%6,%7}, {%8,%9}, {%0,%1,%2,%3};"
        : "+f"(c[0]), "+f"(c[1]), "+f"(c[2]), "+f"(c[3])
        : "r"(a[0]), "r"(a[1]), "r"(a[2]), "r"(a[3]), "r"(b0), "r"(b1));
}
__device__ __forceinline__ void split2(float a, float b, uint32_t& hi, uint32_t& lo) {
    bf16 ha = __float2bfloat16(a), hb = __float2bfloat16(b);
    bf16 la = __float2bfloat16(a - __bfloat162float(ha));
    bf16 lb = __float2bfloat16(b - __bfloat162float(hb));
    __nv_bfloat162 h(ha, hb), l(la, lb);
    hi = *(uint32_t*)&h; lo = *(uint32_t*)&l;
}
// cheap truncation split: hi = packed high-16 bits (RZ bf16), lo = residual RN bf16x2
__device__ __forceinline__ void split2t(float a, float b, uint32_t& hi, uint32_t& lo) {
    uint32_t ia = __float_as_uint(a), ib = __float_as_uint(b);
    hi = __byte_perm(ia, ib, 0x7632);
    float fa = __uint_as_float(ia & 0xFFFF0000u);
    float fb = __uint_as_float(ib & 0xFFFF0000u);
    float la = a - fa, lb = b - fb;
    asm("cvt.rn.bf16x2.f32 %0, %1, %2;" : "=r"(lo) : "f"(lb), "f"(la));
}
// RNA round a fragment register (fp32 bits) to tf32-exact (b32 in/out)
__device__ __forceinline__ uint32_t rna_r(uint32_t v) {
    uint32_t o;
    asm("cvt.rna.tf32.f32 %0, %1;" : "=r"(o) : "r"(v));
    return o;
}
__device__ __forceinline__ void rna4(uint32_t* r) {
    r[0] = rna_r(r[0]); r[1] = rna_r(r[1]); r[2] = rna_r(r[2]); r[3] = rna_r(r[3]);
}
// 16B-chunk XOR swizzle for 32-float (128B) rows: chunk 0..7, rows 0..127
__device__ __forceinline__ uint32_t swzf(int row, int chunk) {
    return (uint32_t)(row * 128 + ((chunk ^ (row & 7)) << 4));
}
// 16B-chunk XOR swizzle for 128-bf16 (256B) rows: chunk 0..15, rows 0..63
__device__ __forceinline__ uint32_t swzb(int row, int chunk) {
    return (uint32_t)(row * 256 + ((chunk ^ (row & 7)) << 4));
}

// ============================================================
// tf32 GEMM: C[M,N] = A @ B^T + bias, A/B raw fp32 (RNA-rounded
// in registers after ldmatrix -> numerics identical to pre-prep).
// CTA 128x128, BK=32, 3-stage cp.async, 1 sync/iter, 2 CTAs/SM,
// 4 warps 2x2 (64x64/warp).
// ============================================================
#define TOFF_A 0
#define TOFF_B (128*128)
#define TSTAGE (2*128*128)       // 32768 B
#define TGSMEM (3*TSTAGE)        // 98304 B
#define GT 128

struct GemmPtrs {
    const float* B[3];
    const float* bias[3];
    bf16* Ch[3];
    bf16* Cl[3];
    float* C[3];
};

__device__ __forceinline__ void t_load_tile(uint32_t sbase, const float* g,
                                            int row0, int k0, int tid)
{
    const char* gp = (const char*)(g + (size_t)row0 * Hsz + k0);
    #pragma unroll
    for (int c = tid; c < 1024; c += GT) {
        int row = c >> 3, ch = c & 7;
        CP_ASYNC16(sbase + swzf(row, ch), gp + (size_t)row * (Hsz * 4) + ch * 16);
    }
}
__device__ __forceinline__ void t_load_stage(uint32_t st, const float* A, const float* B,
                                             int bm, int bn, int k0, int tid)
{
    t_load_tile(st + TOFF_A, A, bm, k0, tid);
    t_load_tile(st + TOFF_B, B, bn, k0, tid);
}

template <bool BF16OUT>
__global__ void __launch_bounds__(GT, 2)
gemm_tf32(const float* __restrict__ A, GemmPtrs p)
{
    extern __shared__ __align__(128) char sm[];
    const uint32_t sb = smem_u32(sm);
    const int tid  = threadIdx.x;
    const int lane = tid & 31;
    const int wid  = tid >> 5;
    const int wm   = wid >> 1;
    const int wn   = wid & 1;
    const int region = blockIdx.x >> 4;
    const int bm = blockIdx.y * 128;
    const int bn = (blockIdx.x & 15) * 128;
    const float* Bm = p.B[region];

    float acc[4][8][4];
    #pragma unroll
    for (int i = 0; i < 4; i++)
        #pragma unroll
        for (int j = 0; j < 8; j++)
            #pragma unroll
            for (int t = 0; t < 4; t++) acc[i][j][t] = 0.f;

    t_load_stage(sb,          A, Bm, bm, bn, 0,  tid); CP_COMMIT();
    t_load_stage(sb + TSTAGE, A, Bm, bm, bn, 32, tid); CP_COMMIT();

    const int g  = lane >> 3;
    const int t8 = lane & 7;

    for (int kt = 0; kt < 64; kt++) {
        if (kt < 63) { CP_WAIT(1); } else { CP_WAIT(0); }
        __syncthreads();

        if (kt + 2 < 64) {
            t_load_stage(sb + ((kt + 2) % 3) * TSTAGE, A, Bm, bm, bn, (kt + 2) * 32, tid);
            CP_COMMIT();
        }

        const uint32_t st = sb + (kt % 3) * TSTAGE;
        #pragma unroll
        for (int kk = 0; kk < 4; kk++) {
            uint32_t af[4][4];
            #pragma unroll
            for (int mi = 0; mi < 4; mi++) {
                int row = wm * 64 + mi * 16 + t8 + ((g & 1) << 3);
                int ch  = kk * 2 + (g >> 1);
                ldsm4(af[mi], st + TOFF_A + swzf(row, ch));
                rna4(af[mi]);                   // RNA-round in registers
            }
            uint32_t bfr[4][4];
            #pragma unroll
            for (int pj = 0; pj < 4; pj++) {
                int row = wn * 64 + (2 * pj + (g >> 1)) * 8 + t8;
                int ch  = kk * 2 + (g & 1);
                ldsm4(bfr[pj], st + TOFF_B + swzf(row, ch));
                rna4(bfr[pj]);                  // RNA-round in registers
            }
            #pragma unroll
            for (int mi = 0; mi < 4; mi++) {
                #pragma unroll
                for (int nj = 0; nj < 8; nj++) {
                    const uint32_t* bp = bfr[nj >> 1] + (nj & 1) * 2;
                    mma1688t(acc[mi][nj], af[mi], bp[0], bp[1]);
                }
            }
        }
    }

    const int rbase = bm + wm * 64 + (lane >> 2);
    const int cbase = bn + wn * 64 + (lane & 3) * 2;
    const float* bias = p.bias[region];
    #pragma unroll
    for (int mi = 0; mi < 4; mi++) {
        #pragma unroll
        for (int nj = 0; nj < 8; nj++) {
            int row = rbase + mi * 16;
            int col = cbase + nj * 8;
            float b0 = __ldg(&bias[col]), b1 = __ldg(&bias[col + 1]);
            float* c = acc[mi][nj];
            float v00 = c[0] + b0, v01 = c[1] + b1;
            float v10 = c[2] + b0, v11 = c[3] + b1;
            if (BF16OUT) {
                bf16* Ch = p.Ch[region];
                bf16* Cl = p.Cl[region];
                uint32_t h, l;
                split2(v00, v01, h, l);
                *(uint32_t*)(Ch + (size_t)row * Hsz + col) = h;
                *(uint32_t*)(Cl + (size_t)row * Hsz + col) = l;
                split2(v10, v11, h, l);
                *(uint32_t*)(Ch + (size_t)(row + 8) * Hsz + col) = h;
                *(uint32_t*)(Cl + (size_t)(row + 8) * Hsz + col) = l;
            } else {
                float* C = p.C[region];
                *(float2*)(C + (size_t)row * Hsz + col) = make_float2(v00, v01);
                *(float2*)(C + (size_t)(row + 8) * Hsz + col) = make_float2(v10, v11);
            }
        }
    }
}

// ============================================================
// Flash attention via mma.sync, 3-pass split on QK and PV.
// BQ=64, BKV=64, 128 threads (4 warps x 16 query rows), 2 CTAs/SM.
// K double-buffered + V single; CP_WAIT -> sync -> read at both points.
// ============================================================
#define KTILE 16384               // one 64x128 bf16 tile, swizzled 256B rows
#define KB0   0
#define KB1   (2*KTILE)
#define VB    (4*KTILE)
#define ASMEM (6*KTILE)           // 98304 per CTA, 2 CTAs/SM
#define FT 128

__device__ __forceinline__ void fa_load64s(uint32_t sbase, const bf16* g, size_t gelem, int tid) {
    const char* gp = (const char*)(g + gelem);
    #pragma unroll
    for (int c = tid; c < 1024; c += FT) {
        int r = c >> 4, ch = c & 15;
        CP_ASYNC16(sbase + swzb(r, ch), gp + (size_t)r * (Hsz * 2) + ch * 16);
    }
}

__global__ void __launch_bounds__(FT, 2)
flash_mma(const bf16* __restrict__ Qh, const bf16* __restrict__ Ql,
          const bf16* __restrict__ Kh, const bf16* __restrict__ Kl,
          const bf16* __restrict__ Vh, const bf16* __restrict__ Vl,
          float* __restrict__ AO)
{
    extern __shared__ __align__(128) char sm[];
    const uint32_t sb = smem_u32(sm);
    const int tid = threadIdx.x;
    const int lane = tid & 31;
    const int w = tid >> 5;
    const int wrow = w * 16;
    const int qb = gridDim.x - 1 - blockIdx.x;   // heavy-first
    const int h = blockIdx.y, b = blockIdx.z;
    const int q0 = qb * 64;
    const size_t baseKV = (size_t)(b * Ssz) * Hsz + h * HDIM;
    const size_t baseQ  = baseKV + (size_t)q0 * Hsz;

    const int a_row = lane & 15;
    const int a_ch  = lane >> 4;
    const int b_row = ((lane >> 4) & 1) * 8 + (lane & 7);
    const int b_ch  = (lane >> 3) & 1;
    const int t_row = lane & 15;
    const int t_ch  = lane >> 4;

    // ---- load Q hi->KB0 and lo->KB1 concurrently, single sync round ----
    uint32_t qfh[8][4], qfl[8][4];
    fa_load64s(sb + KB0, Qh, baseQ, tid);
    fa_load64s(sb + KB1, Ql, baseQ, tid);
    CP_COMMIT(); CP_WAIT(0); __syncthreads();
    #pragma unroll
    for (int t = 0; t < 8; t++) {
        ldsm4(qfh[t], sb + KB0 + swzb(wrow + a_row, a_ch + t * 2));
        ldsm4(qfl[t], sb + KB1 + swzb(wrow + a_row, a_ch + t * 2));
    }
    __syncthreads();

    // prologue: K(0) -> KB0
    fa_load64s(sb + KB0,         Kh, baseKV, tid);
    fa_load64s(sb + KB0 + KTILE, Kl, baseKV, tid);
    CP_COMMIT();

    float o[16][4];
    #pragma unroll
    for (int j = 0; j < 16; j++)
        #pragma unroll
        for (int t = 0; t < 4; t++) o[j][t] = 0.f;
    float m_i[2] = {-1e30f, -1e30f}, l_i[2] = {0.f, 0.f};

    const int ktmax = qb;
    const int r0 = lane >> 2;
    const float sc2 = 0.1275174112f;   // (1/sqrt(128)) * log2(e)

    // Loop invariant at top: pending cp.async groups = { K(kt) } only.
    for (int kt = 0; kt <= ktmax; kt++) {
        CP_WAIT(0);                // my K(kt) copies complete
        __syncthreads();           // K(kt) visible; V buf + other K buf free

        fa_load64s(sb + VB,         Vh, baseKV + (size_t)(kt * 64) * Hsz, tid);
        fa_load64s(sb + VB + KTILE, Vl, baseKV + (size_t)(kt * 64) * Hsz, tid);
        CP_COMMIT();
        const bool more = kt < ktmax;
        if (more) {
            uint32_t kb = sb + (((kt + 1) & 1) ? KB1 : KB0);
            fa_load64s(kb,         Kh, baseKV + (size_t)((kt + 1) * 64) * Hsz, tid);
            fa_load64s(kb + KTILE, Kl, baseKV + (size_t)((kt + 1) * 64) * Hsz, tid);
            CP_COMMIT();
        }

        // ---- QK from kbuf[kt&1] ----
        const uint32_t kb = sb + ((kt & 1) ? KB1 : KB0);
        float s[8][4];
        #pragma unroll
        for (int j = 0; j < 8; j++)
            #pragma unroll
            for (int t = 0; t < 4; t++) s[j][t] = 0.f;
        #pragma unroll
        for (int t = 0; t < 8; t++) {
            uint32_t kbh[4][4], kbl[4][4];
            #pragma unroll
            for (int pp = 0; pp < 4; pp++) {
                uint32_t ra = swzb(pp * 16 + b_row, b_ch + t * 2);
                ldsm4(kbh[pp], kb + ra);
                ldsm4(kbl[pp], kb + KTILE + ra);
            }
            #pragma unroll
            for (int pp = 0; pp < 4; pp++) {
                #pragma unroll
                for (int hh = 0; hh < 2; hh++) {
                    mma16816(s[2*pp+hh], qfh[t], kbh[pp][hh*2], kbh[pp][hh*2+1]);
                    mma16816(s[2*pp+hh], qfh[t], kbl[pp][hh*2], kbl[pp][hh*2+1]);
                    mma16816(s[2*pp+hh], qfl[t], kbh[pp][hh*2], kbh[pp][hh*2+1]);
                }
            }
        }

        // ---- softmax (exp2 domain) ----
        uint32_t pah[4][4], pal[4][4];
        float fac[2];
        {
            #pragma unroll
            for (int j = 0; j < 8; j++)
                #pragma unroll
                for (int t = 0; t < 4; t++) s[j][t] *= sc2;
            if (kt == ktmax) {
                #pragma unroll
                for (int j = 0; j < 8; j++) {
                    int col = kt * 64 + j * 8 + (lane & 3) * 2;
                    int row = q0 + wrow + r0;
                    if (col > row)          s[j][0] = -1e30f;
                    if (col + 1 > row)      s[j][1] = -1e30f;
                    if (col > row + 8)      s[j][2] = -1e30f;
                    if (col + 1 > row + 8)  s[j][3] = -1e30f;
                }
            }
            #pragma unroll
            for (int r = 0; r < 2; r++) {
                float rm = -1e30f;
                #pragma unroll
                for (int j = 0; j < 8; j++) rm = fmaxf(rm, fmaxf(s[j][r*2], s[j][r*2+1]));
                rm = fmaxf(rm, __shfl_xor_sync(0xffffffffu, rm, 1));
                rm = fmaxf(rm, __shfl_xor_sync(0xffffffffu, rm, 2));
                float mn = fmaxf(m_i[r], rm);
                fac[r] = exp2f(m_i[r] - mn);
                float rs = 0.f;
                #pragma unroll
                for (int j = 0; j < 8; j++) {
                    s[j][r*2]   = exp2f(s[j][r*2]   - mn);
                    s[j][r*2+1] = exp2f(s[j][r*2+1] - mn);
                    rs += s[j][r*2] + s[j][r*2+1];
                }
                rs += __shfl_xor_sync(0xffffffffu, rs, 1);
                rs += __shfl_xor_sync(0xffffffffu, rs, 2);
                l_i[r] = l_i[r] * fac[r] + rs;
                m_i[r] = mn;
            }
            #pragma unroll
            for (int t2 = 0; t2 < 4; t2++) {
                split2t(s[2*t2][0],   s[2*t2][1],   pah[t2][0], pal[t2][0]);
                split2t(s[2*t2][2],   s[2*t2][3],   pah[t2][1], pal[t2][1]);
                split2t(s[2*t2+1][0], s[2*t2+1][1], pah[t2][2], pal[t2][2]);
                split2t(s[2*t2+1][2], s[2*t2+1][3], pah[t2][3], pal[t2][3]);
            }
            #pragma unroll
            for (int j = 0; j < 16; j++) {
                o[j][0] *= fac[0]; o[j][1] *= fac[0];
                o[j][2] *= fac[1]; o[j][3] *= fac[1];
            }
        }

        // V(kt) complete (K(kt+1) may remain in flight)
        if (more) { CP_WAIT(1); } else { CP_WAIT(0); }
        __syncthreads();

        // ---- PV from V buffer ----
        #pragma unroll
        for (int j2 = 0; j2 < 8; j2++) {
            #pragma unroll
            for (int t = 0; t < 4; t++) {
                uint32_t bvh[4], bvl[4];
                uint32_t ra = swzb(t * 16 + t_row, t_ch + j2 * 2);
                ldsm4t(bvh, sb + VB + ra);
                ldsm4t(bvl, sb + VB + KTILE + ra);
                mma16816(o[2*j2],   pah[t], bvh[0], bvh[1]);
                mma16816(o[2*j2+1], pah[t], bvh[2], bvh[3]);
                mma16816(o[2*j2],   pah[t], bvl[0], bvl[1]);
                mma16816(o[2*j2+1], pah[t], bvl[2], bvl[3]);
                mma16816(o[2*j2],   pal[t], bvh[0], bvh[1]);
                mma16816(o[2*j2+1], pal[t], bvh[2], bvh[3]);
            }
        }
    }

    // epilogue: normalize (raw fp32; O-proj RNA-rounds its own fragments)
    const float inv0 = 1.0f / l_i[0], inv1 = 1.0f / l_i[1];
    const int grow0 = q0 + wrow + r0;
    #pragma unroll
    for (int j = 0; j < 16; j++) {
        int col = j * 8 + (lane & 3) * 2;
        size_t e0 = baseKV + (size_t)grow0 * Hsz + col;
        size_t e1 = baseKV + (size_t)(grow0 + 8) * Hsz + col;
        *(float2*)(AO + e0) = make_float2(o[j][0] * inv0, o[j][1] * inv0);
        *(float2*)(AO + e1) = make_float2(o[j][2] * inv1, o[j][3] * inv1);
    }
}

// ============================================================
extern "C" void kernel_launch(void* const* d_in, const int* in_sizes, int n_in,
                              void* d_out, int out_size) {
    const float* x  = (const float*)d_in[0];
    const float* Wf[4] = { (const float*)d_in[1], (const float*)d_in[3],
                           (const float*)d_in[5], (const float*)d_in[7] };
    const float* bQ = (const float*)d_in[2];
    const float* bK = (const float*)d_in[4];
    const float* bV = (const float*)d_in[6];
    const float* bO = (const float*)d_in[8];
    float* out = (float*)d_out;

    float *ao;
    bf16 *qh, *ql, *kh, *kl, *vh, *vl;
    cudaGetSymbolAddress((void**)&ao, g_ao);
    cudaGetSymbolAddress((void**)&qh, g_qh);  cudaGetSymbolAddress((void**)&ql, g_ql);
    cudaGetSymbolAddress((void**)&kh, g_kh);  cudaGetSymbolAddress((void**)&kl, g_kl);
    cudaGetSymbolAddress((void**)&vh, g_vh);  cudaGetSymbolAddress((void**)&vl, g_vl);

    cudaFuncSetAttribute(gemm_tf32<true>,  cudaFuncAttributeMaxDynamicSharedMemorySize, TGSMEM);
    cudaFuncSetAttribute(gemm_tf32<false>, cudaFuncAttributeMaxDynamicSharedMemorySize, TGSMEM);

    // Launch 1: fused QKV tf32 GEMM on raw inputs (in-register RNA rounding)
    GemmPtrs pq;
    pq.B[0] = Wf[0];        pq.B[1] = Wf[1];        pq.B[2] = Wf[2];
    pq.bias[0] = bQ;        pq.bias[1] = bK;        pq.bias[2] = bV;
    pq.Ch[0] = qh;          pq.Ch[1] = kh;          pq.Ch[2] = vh;
    pq.Cl[0] = ql;          pq.Cl[1] = kl;          pq.Cl[2] = vl;
    pq.C[0] = pq.C[1] = pq.C[2] = nullptr;
    gemm_tf32<true><<<dim3(48, Mrows / 128), GT, TGSMEM>>>(x, pq);

    // Launch 2: attention (bf16 3-pass, K double-buffered)
    cudaFuncSetAttribute(flash_mma, cudaFuncAttributeMaxDynamicSharedMemorySize, ASMEM);
    flash_mma<<<dim3(Ssz / 64, NHEAD, Bsz), FT, ASMEM>>>(qh, ql, kh, kl, vh, vl, ao);

    // Launch 3: output projection (tf32, fp32 out)
    GemmPtrs po;
    po.B[0] = Wf[3];        po.B[1] = po.B[2] = nullptr;
    po.bias[0] = bO;        po.bias[1] = po.bias[2] = nullptr;
    po.Ch[0] = po.Ch[1] = po.Ch[2] = nullptr;
    po.Cl[0] = po.Cl[1] = po.Cl[2] = nullptr;
    po.C[0] = out;          po.C[1] = po.C[2] = nullptr;
    gemm_tf32<false><<<dim3(16, Mrows / 128), GT, TGSMEM>>>(ao, po);
}

// round 16
// speedup vs baseline: 1.0538x; 1.0538x over previous
#include <cuda_runtime.h>
#include <cuda_bf16.h>
#include <cstdint>

// Problem dims
#define Bsz   2
#define Ssz   2048
#define Hsz   2048
#define NHEAD 16
#define HDIM  128
#define Mrows (Bsz*Ssz)   // 4096

typedef __nv_bfloat16 bf16;

// ---------------- scratch (static device globals) ----------------
__device__ float g_xt [Mrows*Hsz];          // RNA-rounded x
__device__ float g_wt [4][Hsz*Hsz];         // RNA-rounded weights
__device__ float g_ao [Mrows*Hsz];          // attention out (RNA-rounded)
__device__ bf16 g_qh [Mrows*Hsz], g_ql [Mrows*Hsz];
__device__ bf16 g_kh [Mrows*Hsz], g_kl [Mrows*Hsz];
__device__ bf16 g_vh [Mrows*Hsz], g_vl [Mrows*Hsz];

// ---------------- helpers ----------------
__device__ __forceinline__ uint32_t smem_u32(const void* p) {
    uint32_t a;
    asm("{ .reg .u64 t; cvta.to.shared.u64 t, %1; cvt.u32.u64 %0, t; }" : "=r"(a) : "l"(p));
    return a;
}
#define CP_ASYNC16(sa, ga) \
    asm volatile("cp.async.cg.shared.global [%0], [%1], 16;" :: "r"((uint32_t)(sa)), "l"(ga))
#define CP_COMMIT() asm volatile("cp.async.commit_group;" ::: "memory")
#define CP_WAIT(n)  asm volatile("cp.async.wait_group %0;" :: "n"(n) : "memory")

__device__ __forceinline__ void ldsm4(uint32_t* r, uint32_t addr) {
    asm volatile("ldmatrix.sync.aligned.m8n8.x4.shared.b16 {%0,%1,%2,%3}, [%4];"
                 : "=r"(r[0]), "=r"(r[1]), "=r"(r[2]), "=r"(r[3]) : "r"(addr));
}
__device__ __forceinline__ void ldsm4t(uint32_t* r, uint32_t addr) {
    asm volatile("ldmatrix.sync.aligned.m8n8.x4.trans.shared.b16 {%0,%1,%2,%3}, [%4];"
                 : "=r"(r[0]), "=r"(r[1]), "=r"(r[2]), "=r"(r[3]) : "r"(addr));
}
// bf16 mma (flash)
__device__ __forceinline__ void mma16816(float* c, const uint32_t* a,
                                         uint32_t b0, uint32_t b1) {
    asm volatile(
        "mma.sync.aligned.m16n8k16.row.col.f32.bf16.bf16.f32 "
        "{%0,%1,%2,%3}, {%4,%5,%6,%7}, {%8,%9}, {%0,%1,%2,%3};"
        : "+f"(c[0]), "+f"(c[1]), "+f"(c[2]), "+f"(c[3])
        : "r"(a[0]), "r"(a[1]), "r"(a[2]), "r"(a[3]), "r"(b0), "r"(b1));
}
// tf32 mma (projections)
__device__ __forceinline__ void mma1688t(float* c, const uint32_t* a,
                                         uint32_t b0, uint32_t b1) {
    asm volatile(
        "mma.sync.aligned.m16n8k8.row.col.f32.tf32.tf32.f32 "
        "{%0,%1,%2,%3}, {%4,%5,%6,%7}, {%8,%9}, {%0,%1,%2,%3};"
        : "+f"(c[0]), "+f"(c[1]), "+f"(c[2]), "+f"(c[3])
        : "r"(a[0]), "r"(a[1]), "r"(a[2]), "r"(a[3]), "r"(b0), "r"(b1));
}
__device__ __forceinline__ void split2(float a, float b, uint32_t& hi, uint32_t& lo) {
    bf16 ha = __float2bfloat16(a), hb = __float2bfloat16(b);
    bf16 la = __float2bfloat16(a - __bfloat162float(ha));
    bf16 lb = __float2bfloat16(b - __bfloat162float(hb));
    __nv_bfloat162 h(ha, hb), l(la, lb);
    hi = *(uint32_t*)&h; lo = *(uint32_t*)&l;
}
// cheap truncation split: hi = packed high-16 bits (RZ bf16), lo = residual RN bf16x2
__device__ __forceinline__ void split2t(float a, float b, uint32_t& hi, uint32_t& lo) {
    uint32_t ia = __float_as_uint(a), ib = __float_as_uint(b);
    hi = __byte_perm(ia, ib, 0x7632);
    float fa = __uint_as_float(ia & 0xFFFF0000u);
    float fb = __uint_as_float(ib & 0xFFFF0000u);
    float la = a - fa, lb = b - fb;
    asm("cvt.rn.bf16x2.f32 %0, %1, %2;" : "=r"(lo) : "f"(lb), "f"(la));
}
// RNA round to tf32-exact fp32. tf32 lives in b32 registers in PTX -> "=r".
__device__ __forceinline__ float rna_tf32(float v) {
    uint32_t o;
    asm("cvt.rna.tf32.f32 %0, %1;" : "=r"(o) : "f"(v));
    return __uint_as_float(o);
}
// raw MUFU exp2 (approx; rel err ~2^-22, invisible under bf16 P-split)
__device__ __forceinline__ float ex2(float x) {
    float o;
    asm("ex2.approx.ftz.f32 %0, %1;" : "=f"(o) : "f"(x));
    return o;
}
// 16B-chunk XOR swizzle for 32-float (128B) rows: chunk 0..7, rows 0..127
__device__ __forceinline__ uint32_t swzf(int row, int chunk) {
    return (uint32_t)(row * 128 + ((chunk ^ (row & 7)) << 4));
}
// 16B-chunk XOR swizzle for 128-bf16 (256B) rows: chunk 0..15, rows 0..63
__device__ __forceinline__ uint32_t swzb(int row, int chunk) {
    return (uint32_t)(row * 256 + ((chunk ^ (row & 7)) << 4));
}

// ============================================================
// Prep: RNA-round fp32 -> tf32-exact fp32 copies (x + 4 weights)
// ============================================================
struct PrepJobs {
    const float4* in[5];
    float4* out[5];
    int n4[5];
    int blk0[5];
};

__global__ void prep_tf32(PrepJobs j, int totblk)
{
    int r = 0;
    #pragma unroll
    for (int i = 1; i < 5; i++) if ((int)blockIdx.x >= j.blk0[i]) r = i;
    const int rel  = blockIdx.x - j.blk0[r];
    const int nblk = ((r + 1 < 5) ? j.blk0[r + 1] : totblk) - j.blk0[r];
    const float4* in = j.in[r];
    float4* out = j.out[r];
    const int n4 = j.n4[r];
    for (int i = rel * blockDim.x + threadIdx.x; i < n4; i += nblk * blockDim.x) {
        float4 v = in[i];
        v.x = rna_tf32(v.x); v.y = rna_tf32(v.y);
        v.z = rna_tf32(v.z); v.w = rna_tf32(v.w);
        out[i] = v;
    }
}

// ============================================================
// tf32 GEMM: C[M,N] = A @ B^T + bias.  CTA 128x128, BK=32,
// 3-stage cp.async, 1 sync/iter, 2 CTAs/SM, 4 warps 2x2 (64x64/warp).
// Operands pre-rounded by prep (clean ldsm->mma path).
// ============================================================
#define TOFF_A 0
#define TOFF_B (128*128)
#define TSTAGE (2*128*128)       // 32768 B
#define TGSMEM (3*TSTAGE)        // 98304 B
#define GT 128

struct GemmPtrs {
    const float* B[3];
    const float* bias[3];
    bf16* Ch[3];
    bf16* Cl[3];
    float* C[3];
};

__device__ __forceinline__ void t_load_tile(uint32_t sbase, const float* g,
                                            int row0, int k0, int tid)
{
    const char* gp = (const char*)(g + (size_t)row0 * Hsz + k0);
    #pragma unroll
    for (int c = tid; c < 1024; c += GT) {
        int row = c >> 3, ch = c & 7;
        CP_ASYNC16(sbase + swzf(row, ch), gp + (size_t)row * (Hsz * 4) + ch * 16);
    }
}
__device__ __forceinline__ void t_load_stage(uint32_t st, const float* A, const float* B,
                                             int bm, int bn, int k0, int tid)
{
    t_load_tile(st + TOFF_A, A, bm, k0, tid);
    t_load_tile(st + TOFF_B, B, bn, k0, tid);
}

template <bool BF16OUT>
__global__ void __launch_bounds__(GT, 2)
gemm_tf32(const float* __restrict__ A, GemmPtrs p)
{
    extern __shared__ __align__(128) char sm[];
    const uint32_t sb = smem_u32(sm);
    const int tid  = threadIdx.x;
    const int lane = tid & 31;
    const int wid  = tid >> 5;
    const int wm   = wid >> 1;
    const int wn   = wid & 1;
    const int region = blockIdx.x >> 4;
    const int bm = blockIdx.y * 128;
    const int bn = (blockIdx.x & 15) * 128;
    const float* Bm = p.B[region];

    float acc[4][8][4];
    #pragma unroll
    for (int i = 0; i < 4; i++)
        #pragma unroll
        for (int j = 0; j < 8; j++)
            #pragma unroll
            for (int t = 0; t < 4; t++) acc[i][j][t] = 0.f;

    t_load_stage(sb,          A, Bm, bm, bn, 0,  tid); CP_COMMIT();
    t_load_stage(sb + TSTAGE, A, Bm, bm, bn, 32, tid); CP_COMMIT();

    const int g  = lane >> 3;
    const int t8 = lane & 7;

    for (int kt = 0; kt < 64; kt++) {
        if (kt < 63) { CP_WAIT(1); } else { CP_WAIT(0); }
        __syncthreads();

        if (kt + 2 < 64) {
            t_load_stage(sb + ((kt + 2) % 3) * TSTAGE, A, Bm, bm, bn, (kt + 2) * 32, tid);
            CP_COMMIT();
        }

        const uint32_t st = sb + (kt % 3) * TSTAGE;
        #pragma unroll
        for (int kk = 0; kk < 4; kk++) {
            uint32_t af[4][4];
            #pragma unroll
            for (int mi = 0; mi < 4; mi++) {
                int row = wm * 64 + mi * 16 + t8 + ((g & 1) << 3);
                int ch  = kk * 2 + (g >> 1);
                ldsm4(af[mi], st + TOFF_A + swzf(row, ch));
            }
            uint32_t bfr[4][4];
            #pragma unroll
            for (int pj = 0; pj < 4; pj++) {
                int row = wn * 64 + (2 * pj + (g >> 1)) * 8 + t8;
                int ch  = kk * 2 + (g & 1);
                ldsm4(bfr[pj], st + TOFF_B + swzf(row, ch));
            }
            #pragma unroll
            for (int mi = 0; mi < 4; mi++) {
                #pragma unroll
                for (int nj = 0; nj < 8; nj++) {
                    const uint32_t* bp = bfr[nj >> 1] + (nj & 1) * 2;
                    mma1688t(acc[mi][nj], af[mi], bp[0], bp[1]);
                }
            }
        }
    }

    const int rbase = bm + wm * 64 + (lane >> 2);
    const int cbase = bn + wn * 64 + (lane & 3) * 2;
    const float* bias = p.bias[region];
    #pragma unroll
    for (int mi = 0; mi < 4; mi++) {
        #pragma unroll
        for (int nj = 0; nj < 8; nj++) {
            int row = rbase + mi * 16;
            int col = cbase + nj * 8;
            float b0 = __ldg(&bias[col]), b1 = __ldg(&bias[col + 1]);
            float* c = acc[mi][nj];
            float v00 = c[0] + b0, v01 = c[1] + b1;
            float v10 = c[2] + b0, v11 = c[3] + b1;
            if (BF16OUT) {
                bf16* Ch = p.Ch[region];
                bf16* Cl = p.Cl[region];
                uint32_t h, l;
                split2(v00, v01, h, l);
                *(uint32_t*)(Ch + (size_t)row * Hsz + col) = h;
                *(uint32_t*)(Cl + (size_t)row * Hsz + col) = l;
                split2(v10, v11, h, l);
                *(uint32_t*)(Ch + (size_t)(row + 8) * Hsz + col) = h;
                *(uint32_t*)(Cl + (size_t)(row + 8) * Hsz + col) = l;
            } else {
                float* C = p.C[region];
                *(float2*)(C + (size_t)row * Hsz + col) = make_float2(v00, v01);
                *(float2*)(C + (size_t)(row + 8) * Hsz + col) = make_float2(v10, v11);
            }
        }
    }
}

// ============================================================
// Flash attention via mma.sync, 3-pass split on QK and PV.
// BQ=64, BKV=64, 128 threads (4 warps x 16 query rows), 2 CTAs/SM.
// K double-buffered + V single; CP_WAIT -> sync -> read at both points.
// ex2.approx softmax; truncation split for P; RNA-rounded AO out.
// ============================================================
#define KTILE 16384               // one 64x128 bf16 tile, swizzled 256B rows
#define KB0   0
#define KB1   (2*KTILE)
#define VB    (4*KTILE)
#define ASMEM (6*KTILE)           // 98304 per CTA, 2 CTAs/SM
#define FT 128

__device__ __forceinline__ void fa_load64s(uint32_t sbase, const bf16* g, size_t gelem, int tid) {
    const char* gp = (const char*)(g + gelem);
    #pragma unroll
    for (int c = tid; c < 1024; c += FT) {
        int r = c >> 4, ch = c & 15;
        CP_ASYNC16(sbase + swzb(r, ch), gp + (size_t)r * (Hsz * 2) + ch * 16);
    }
}

__global__ void __launch_bounds__(FT, 2)
flash_mma(const bf16* __restrict__ Qh, const bf16* __restrict__ Ql,
          const bf16* __restrict__ Kh, const bf16* __restrict__ Kl,
          const bf16* __restrict__ Vh, const bf16* __restrict__ Vl,
          float* __restrict__ AO)
{
    extern __shared__ __align__(128) char sm[];
    const uint32_t sb = smem_u32(sm);
    const int tid = threadIdx.x;
    const int lane = tid & 31;
    const int w = tid >> 5;
    const int wrow = w * 16;
    const int qb = gridDim.x - 1 - blockIdx.x;   // heavy-first
    const int h = blockIdx.y, b = blockIdx.z;
    const int q0 = qb * 64;
    const size_t baseKV = (size_t)(b * Ssz) * Hsz + h * HDIM;
    const size_t baseQ  = baseKV + (size_t)q0 * Hsz;

    const int a_row = lane & 15;
    const int a_ch  = lane >> 4;
    const int b_row = ((lane >> 4) & 1) * 8 + (lane & 7);
    const int b_ch  = (lane >> 3) & 1;
    const int t_row = lane & 15;
    const int t_ch  = lane >> 4;

    // ---- load Q hi->KB0 and lo->KB1 concurrently, single sync round ----
    uint32_t qfh[8][4], qfl[8][4];
    fa_load64s(sb + KB0, Qh, baseQ, tid);
    fa_load64s(sb + KB1, Ql, baseQ, tid);
    CP_COMMIT(); CP_WAIT(0); __syncthreads();
    #pragma unroll
    for (int t = 0; t < 8; t++) {
        ldsm4(qfh[t], sb + KB0 + swzb(wrow + a_row, a_ch + t * 2));
        ldsm4(qfl[t], sb + KB1 + swzb(wrow + a_row, a_ch + t * 2));
    }
    __syncthreads();

    // prologue: K(0) -> KB0
    fa_load64s(sb + KB0,         Kh, baseKV, tid);
    fa_load64s(sb + KB0 + KTILE, Kl, baseKV, tid);
    CP_COMMIT();

    float o[16][4];
    #pragma unroll
    for (int j = 0; j < 16; j++)
        #pragma unroll
        for (int t = 0; t < 4; t++) o[j][t] = 0.f;
    float m_i[2] = {-1e30f, -1e30f}, l_i[2] = {0.f, 0.f};

    const int ktmax = qb;
    const int r0 = lane >> 2;
    const float sc2 = 0.1275174112f;   // (1/sqrt(128)) * log2(e)

    // Loop invariant at top: pending cp.async groups = { K(kt) } only.
    for (int kt = 0; kt <= ktmax; kt++) {
        CP_WAIT(0);                // my K(kt) copies complete
        __syncthreads();           // K(kt) visible; V buf + other K buf free

        fa_load64s(sb + VB,         Vh, baseKV + (size_t)(kt * 64) * Hsz, tid);
        fa_load64s(sb + VB + KTILE, Vl, baseKV + (size_t)(kt * 64) * Hsz, tid);
        CP_COMMIT();
        const bool more = kt < ktmax;
        if (more) {
            uint32_t kb = sb + (((kt + 1) & 1) ? KB1 : KB0);
            fa_load64s(kb,         Kh, baseKV + (size_t)((kt + 1) * 64) * Hsz, tid);
            fa_load64s(kb + KTILE, Kl, baseKV + (size_t)((kt + 1) * 64) * Hsz, tid);
            CP_COMMIT();
        }

        // ---- QK from kbuf[kt&1] ----
        const uint32_t kb = sb + ((kt & 1) ? KB1 : KB0);
        float s[8][4];
        #pragma unroll
        for (int j = 0; j < 8; j++)
            #pragma unroll
            for (int t = 0; t < 4; t++) s[j][t] = 0.f;
        #pragma unroll
        for (int t = 0; t < 8; t++) {
            uint32_t kbh[4][4], kbl[4][4];
            #pragma unroll
            for (int pp = 0; pp < 4; pp++) {
                uint32_t ra = swzb(pp * 16 + b_row, b_ch + t * 2);
                ldsm4(kbh[pp], kb + ra);
                ldsm4(kbl[pp], kb + KTILE + ra);
            }
            #pragma unroll
            for (int pp = 0; pp < 4; pp++) {
                #pragma unroll
                for (int hh = 0; hh < 2; hh++) {
                    mma16816(s[2*pp+hh], qfh[t], kbh[pp][hh*2], kbh[pp][hh*2+1]);
                    mma16816(s[2*pp+hh], qfh[t], kbl[pp][hh*2], kbl[pp][hh*2+1]);
                    mma16816(s[2*pp+hh], qfl[t], kbh[pp][hh*2], kbh[pp][hh*2+1]);
                }
            }
        }

        // ---- softmax (exp2 domain, MUFU approx) ----
        uint32_t pah[4][4], pal[4][4];
        float fac[2];
        {
            #pragma unroll
            for (int j = 0; j < 8; j++)
                #pragma unroll
                for (int t = 0; t < 4; t++) s[j][t] *= sc2;
            if (kt == ktmax) {
                #pragma unroll
                for (int j = 0; j < 8; j++) {
                    int col = kt * 64 + j * 8 + (lane & 3) * 2;
                    int row = q0 + wrow + r0;
                    if (col > row)          s[j][0] = -1e30f;
                    if (col + 1 > row)      s[j][1] = -1e30f;
                    if (col > row + 8)      s[j][2] = -1e30f;
                    if (col + 1 > row + 8)  s[j][3] = -1e30f;
                }
            }
            #pragma unroll
            for (int r = 0; r < 2; r++) {
                float rm = -1e30f;
                #pragma unroll
                for (int j = 0; j < 8; j++) rm = fmaxf(rm, fmaxf(s[j][r*2], s[j][r*2+1]));
                rm = fmaxf(rm, __shfl_xor_sync(0xffffffffu, rm, 1));
                rm = fmaxf(rm, __shfl_xor_sync(0xffffffffu, rm, 2));
                float mn = fmaxf(m_i[r], rm);
                fac[r] = ex2(m_i[r] - mn);
                float rs = 0.f;
                #pragma unroll
                for (int j = 0; j < 8; j++) {
                    s[j][r*2]   = ex2(s[j][r*2]   - mn);
                    s[j][r*2+1] = ex2(s[j][r*2+1] - mn);
                    rs += s[j][r*2] + s[j][r*2+1];
                }
                rs += __shfl_xor_sync(0xffffffffu, rs, 1);
                rs += __shfl_xor_sync(0xffffffffu, rs, 2);
                l_i[r] = l_i[r] * fac[r] + rs;
                m_i[r] = mn;
            }
            #pragma unroll
            for (int t2 = 0; t2 < 4; t2++) {
                split2t(s[2*t2][0],   s[2*t2][1],   pah[t2][0], pal[t2][0]);
                split2t(s[2*t2][2],   s[2*t2][3],   pah[t2][1], pal[t2][1]);
                split2t(s[2*t2+1][0], s[2*t2+1][1], pah[t2][2], pal[t2][2]);
                split2t(s[2*t2+1][2], s[2*t2+1][3], pah[t2][3], pal[t2][3]);
            }
            #pragma unroll
            for (int j = 0; j < 16; j++) {
                o[j][0] *= fac[0]; o[j][1] *= fac[0];
                o[j][2] *= fac[1]; o[j][3] *= fac[1];
            }
        }

        // V(kt) complete (K(kt+1) may remain in flight)
        if (more) { CP_WAIT(1); } else { CP_WAIT(0); }
        __syncthreads();

        // ---- PV from V buffer ----
        #pragma unroll
        for (int j2 = 0; j2 < 8; j2++) {
            #pragma unroll
            for (int t = 0; t < 4; t++) {
                uint32_t bvh[4], bvl[4];
                uint32_t ra = swzb(t * 16 + t_row, t_ch + j2 * 2);
                ldsm4t(bvh, sb + VB + ra);
                ldsm4t(bvl, sb + VB + KTILE + ra);
                mma16816(o[2*j2],   pah[t], bvh[0], bvh[1]);
                mma16816(o[2*j2+1], pah[t], bvh[2], bvh[3]);
                mma16816(o[2*j2],   pah[t], bvl[0], bvl[1]);
                mma16816(o[2*j2+1], pah[t], bvl[2], bvl[3]);
                mma16816(o[2*j2],   pal[t], bvh[0], bvh[1]);
                mma16816(o[2*j2+1], pal[t], bvh[2], bvh[3]);
            }
        }
    }

    // epilogue: normalize + RNA-round to tf32-exact fp32 (input of O-proj)
    const float inv0 = 1.0f / l_i[0], inv1 = 1.0f / l_i[1];
    const int grow0 = q0 + wrow + r0;
    #pragma unroll
    for (int j = 0; j < 16; j++) {
        int col = j * 8 + (lane & 3) * 2;
        size_t e0 = baseKV + (size_t)grow0 * Hsz + col;
        size_t e1 = baseKV + (size_t)(grow0 + 8) * Hsz + col;
        *(float2*)(AO + e0) = make_float2(rna_tf32(o[j][0] * inv0), rna_tf32(o[j][1] * inv0));
        *(float2*)(AO + e1) = make_float2(rna_tf32(o[j][2] * inv1), rna_tf32(o[j][3] * inv1));
    }
}

// ============================================================
extern "C" void kernel_launch(void* const* d_in, const int* in_sizes, int n_in,
                              void* d_out, int out_size) {
    const float* x  = (const float*)d_in[0];
    const float* Wf[4] = { (const float*)d_in[1], (const float*)d_in[3],
                           (const float*)d_in[5], (const float*)d_in[7] };
    const float* bQ = (const float*)d_in[2];
    const float* bK = (const float*)d_in[4];
    const float* bV = (const float*)d_in[6];
    const float* bO = (const float*)d_in[8];
    float* out = (float*)d_out;

    float *xt, *wt, *ao;
    bf16 *qh, *ql, *kh, *kl, *vh, *vl;
    cudaGetSymbolAddress((void**)&xt, g_xt);
    cudaGetSymbolAddress((void**)&wt, g_wt);
    cudaGetSymbolAddress((void**)&ao, g_ao);
    cudaGetSymbolAddress((void**)&qh, g_qh);  cudaGetSymbolAddress((void**)&ql, g_ql);
    cudaGetSymbolAddress((void**)&kh, g_kh);  cudaGetSymbolAddress((void**)&kl, g_kl);
    cudaGetSymbolAddress((void**)&vh, g_vh);  cudaGetSymbolAddress((void**)&vl, g_vl);

    const size_t HH = (size_t)Hsz * Hsz;

    // Launch 1: RNA-round x + weights into tf32-exact fp32 copies
    PrepJobs pj;
    pj.in[0]  = (const float4*)x;
    pj.out[0] = (float4*)xt;
    pj.n4[0]  = Mrows * Hsz / 4;
    pj.blk0[0] = 0;
    for (int i = 0; i < 4; i++) {
        pj.in[i+1]  = (const float4*)Wf[i];
        pj.out[i+1] = (float4*)(wt + i * HH);
        pj.n4[i+1]  = Hsz * Hsz / 4;
        pj.blk0[i+1] = 768 + i * 384;
    }
    const int totblk = 768 + 4 * 384;   // 2304
    prep_tf32<<<totblk, 256>>>(pj, totblk);

    cudaFuncSetAttribute(gemm_tf32<true>,  cudaFuncAttributeMaxDynamicSharedMemorySize, TGSMEM);
    cudaFuncSetAttribute(gemm_tf32<false>, cudaFuncAttributeMaxDynamicSharedMemorySize, TGSMEM);

    // Launch 2: fused QKV tf32 GEMM (bf16 hi/lo outputs for flash)
    GemmPtrs pq;
    pq.B[0] = wt;           pq.B[1] = wt + HH;      pq.B[2] = wt + 2 * HH;
    pq.bias[0] = bQ;        pq.bias[1] = bK;        pq.bias[2] = bV;
    pq.Ch[0] = qh;          pq.Ch[1] = kh;          pq.Ch[2] = vh;
    pq.Cl[0] = ql;          pq.Cl[1] = kl;          pq.Cl[2] = vl;
    pq.C[0] = pq.C[1] = pq.C[2] = nullptr;
    gemm_tf32<true><<<dim3(48, Mrows / 128), GT, TGSMEM>>>(xt, pq);

    // Launch 3: attention (bf16 3-pass, K double-buffered)
    cudaFuncSetAttribute(flash_mma, cudaFuncAttributeMaxDynamicSharedMemorySize, ASMEM);
    flash_mma<<<dim3(Ssz / 64, NHEAD, Bsz), FT, ASMEM>>>(qh, ql, kh, kl, vh, vl, ao);

    // Launch 4: output projection (tf32, fp32 out)
    GemmPtrs po;
    po.B[0] = wt + 3 * HH;  po.B[1] = po.B[2] = nullptr;
    po.bias[0] = bO;        po.bias[1] = po.bias[2] = nullptr;
    po.Ch[0] = po.Ch[1] = po.Ch[2] = nullptr;
    po.Cl[0] = po.Cl[1] = po.Cl[2] = nullptr;
    po.C[0] = out;          po.C[1] = po.C[2] = nullptr;
    gemm_tf32<false><<<dim3(16, Mrows / 128), GT, TGSMEM>>>(ao, po);
}